// round 4
// baseline (speedup 1.0000x reference)
#include <cuda_runtime.h>

// FisherLayer: N=8192 rows, D=256 dims, K=32 components.
// out[0:K*D]     = mean_n gamma[n,k]*(y1^2-1)/sqrt(2)
// out[K*D:2*K*D] = mean_n gamma[n,k]*y1
// y1 = w*(x+b), gamma = softmax_k(-0.5*sum_d y1^2).
//
// Factored:
//   y4[n,k]   = -0.5*( sum_d w2*x^2 + sum_d (2*w2*b)*x + c_k ),  c_k = sum_d w2*b^2
//   S0[k]     = sum_n gamma,  Sx[k,d] = sum_n gamma*x,  Sx2[k,d] = sum_n gamma*x^2
//   out_mu    = w*(Sx + b*S0)/N
//   out_sigma = (w2*(Sx2 + 2*b*Sx + b^2*S0) - S0) / (sqrt(2)*N)
//
// 2 kernels, no atomics: main (persistent, 148 blocks) writes per-block
// partials to device scratch; fin reduces 148-way and finalizes.

#define NROWS 8192
#define DD    256
#define KK    32
#define GRID_MAIN 148
#define NBATCH (NROWS / 8)

typedef unsigned long long u64;

// per-block partials: pair-packed (S_{2p}, S_{2p+1}) for d, per block
__device__ __align__(16) u64  g_PX [GRID_MAIN * 16 * DD];   // Sx pairs
__device__ __align__(16) u64  g_PX2[GRID_MAIN * 16 * DD];   // Sx2 pairs
__device__ float              g_PS0[GRID_MAIN * KK];

__device__ __forceinline__ u64 pack2(float lo, float hi) {
    u64 r; asm("mov.b64 %0, {%1, %2};" : "=l"(r) : "f"(lo), "f"(hi)); return r;
}
__device__ __forceinline__ float2 unpack2(u64 v) {
    float2 f; asm("mov.b64 {%0, %1}, %2;" : "=f"(f.x), "=f"(f.y) : "l"(v)); return f;
}
__device__ __forceinline__ u64 fma2(u64 a, u64 b, u64 c) {
    u64 d; asm("fma.rn.f32x2 %0, %1, %2, %3;" : "=l"(d) : "l"(a), "l"(b), "l"(c)); return d;
}

// ---------------- main: persistent blocks, batches of 8 rows ----------------
__global__ void __launch_bounds__(256, 1) fisher_main(const float* __restrict__ x,
                                                      const float* __restrict__ w,
                                                      const float* __restrict__ b) {
    __shared__ __align__(16) u64   s_xx2[2][8 * DD];   // (x^2, x) per [r*D + d]
    __shared__ __align__(16) float s_gamma[8 * KK];    // gamma floats [r][k]
    __shared__ float s_part[8 * 256];                  // y4 partials [slice][r*32+k]
    __shared__ float s_cred[8 * KK];                   // c reduce / s0 reduce

    const int tid  = threadIdx.x;
    const int wrp  = tid >> 5;
    const int lane = tid & 31;

    // ---- inline prep: per-warp slice of (a=w^2, u=2*w^2*b) in regs, c_k reduce ----
    u64 atu[32];
    float c_part = 0.0f;
    {
        const float* wr = w + lane * DD + wrp * 32;
        const float* br = b + lane * DD + wrp * 32;
        #pragma unroll
        for (int j = 0; j < 32; j++) {
            float wv = wr[j], bv = br[j];
            float w2 = wv * wv;
            atu[j] = pack2(w2, 2.0f * w2 * bv);
            c_part += w2 * bv * bv;
        }
    }
    s_cred[wrp * KK + lane] = c_part;

    // accumulators (pair-packed over k): accx[p] = (Sx_{2p}, Sx_{2p+1}) at d=tid
    u64 accx[16], accx2[16];
    #pragma unroll
    for (int p = 0; p < 16; p++) { accx[p] = 0ull; accx2[p] = 0ull; }
    float s0acc = 0.0f;

    int batch = blockIdx.x;
    bool have = true;

    // preload first batch
    float xr[8];
    {
        const float* xb = x + (size_t)batch * 8 * DD;
        #pragma unroll
        for (int r = 0; r < 8; r++) xr[r] = xb[r * DD + tid];
    }

    __syncthreads();
    float c_reg = 0.0f;
    #pragma unroll
    for (int j = 0; j < 8; j++) c_reg += s_cred[j * KK + lane];

    int bufsel = 0;
    while (have) {
        u64* buf = s_xx2[bufsel];
        float cx[8];
        #pragma unroll
        for (int r = 0; r < 8; r++) {
            cx[r] = xr[r];
            buf[r * DD + tid] = pack2(cx[r] * cx[r], cx[r]);
        }

        // prefetch next batch (hidden under compute)
        int nbatch = batch + GRID_MAIN;
        bool nhave = nbatch < NBATCH;
        if (nhave) {
            const float* xb = x + (size_t)nbatch * 8 * DD;
            #pragma unroll
            for (int r = 0; r < 8; r++) xr[r] = xb[r * DD + tid];
        }
        __syncthreads();

        // ---- phase A: y4 partial over this warp's d-slice, 8 rows ----
        {
            u64 accA[8];
            #pragma unroll
            for (int r = 0; r < 8; r++) accA[r] = 0ull;
            #pragma unroll
            for (int j = 0; j < 32; j += 2) {
                const int d0 = wrp * 32 + j;
                #pragma unroll
                for (int r = 0; r < 8; r++) {
                    ulonglong2 v = *reinterpret_cast<const ulonglong2*>(&buf[r * DD + d0]);
                    accA[r] = fma2(atu[j],     v.x, accA[r]);
                    accA[r] = fma2(atu[j + 1], v.y, accA[r]);
                }
            }
            #pragma unroll
            for (int r = 0; r < 8; r++) {
                float2 p = unpack2(accA[r]);
                s_part[wrp * 256 + r * 32 + lane] = p.x + p.y;
            }
        }
        __syncthreads();

        // ---- softmax: warp wrp owns row r=wrp, lane = k ----
        {
            float y = 0.0f;
            #pragma unroll
            for (int j = 0; j < 8; j++) y += s_part[j * 256 + wrp * 32 + lane];
            y = -0.5f * (y + c_reg);
            float m = y;
            #pragma unroll
            for (int o = 16; o; o >>= 1) m = fmaxf(m, __shfl_xor_sync(0xffffffffu, m, o));
            float e = __expf(y - m);
            float s = e;
            #pragma unroll
            for (int o = 16; o; o >>= 1) s += __shfl_xor_sync(0xffffffffu, s, o);
            float g = e / s;
            s0acc += g;
            s_gamma[wrp * KK + lane] = g;
        }
        __syncthreads();

        // ---- phase B: thread owns d=tid; gamma loaded as float pairs ----
        #pragma unroll
        for (int r = 0; r < 8; r++) {
            float xv = cx[r];
            u64 pxx = pack2(xv, xv);
            float x2 = xv * xv;
            u64 px2 = pack2(x2, x2);
            const ulonglong2* grow = reinterpret_cast<const ulonglong2*>(&s_gamma[r * KK]);
            #pragma unroll
            for (int q = 0; q < 8; q++) {
                ulonglong2 gg = grow[q];   // (g4q,g4q+1) , (g4q+2,g4q+3)
                accx [2 * q]     = fma2(gg.x, pxx, accx [2 * q]);
                accx [2 * q + 1] = fma2(gg.y, pxx, accx [2 * q + 1]);
                accx2[2 * q]     = fma2(gg.x, px2, accx2[2 * q]);
                accx2[2 * q + 1] = fma2(gg.y, px2, accx2[2 * q + 1]);
            }
        }

        batch = nbatch;
        have = nhave;
        bufsel ^= 1;
    }

    // ---- S0 cross-warp combine, then write per-block partials ----
    __syncthreads();
    s_cred[wrp * KK + lane] = s0acc;
    __syncthreads();
    if (wrp == 0) {
        float v = 0.0f;
        #pragma unroll
        for (int j = 0; j < 8; j++) v += s_cred[j * KK + lane];
        g_PS0[blockIdx.x * KK + lane] = v;
    }
    {
        u64* px  = g_PX  + (size_t)blockIdx.x * 16 * DD;
        u64* px2 = g_PX2 + (size_t)blockIdx.x * 16 * DD;
        #pragma unroll
        for (int p = 0; p < 16; p++) {
            px [p * DD + tid] = accx[p];
            px2[p * DD + tid] = accx2[p];
        }
    }
}

// ---------------- fin: 148-way reduce + finalize ----------------
// 4096 tasks = (p,d); 8 threads/task: lanes sub 0..3 reduce Sx (stride-4 over
// blocks), sub 4..7 reduce Sx2; shfl combine; sub==0 writes 4 outputs.
__global__ void __launch_bounds__(256) fisher_fin(const float* __restrict__ w,
                                                  const float* __restrict__ b,
                                                  float* __restrict__ out) {
    __shared__ float s_tmp[8 * KK];
    __shared__ float s_S0[KK];

    const int tid = threadIdx.x;
    // block-local S0 reduce (redundant per block, cheap: 19KB L2-hot)
    {
        int lane = tid & 31, g8 = tid >> 5;
        float v = 0.0f;
        for (int bb = g8; bb < GRID_MAIN; bb += 8) v += g_PS0[bb * KK + lane];
        s_tmp[g8 * KK + lane] = v;
        __syncthreads();
        if (tid < KK) {
            float s = 0.0f;
            #pragma unroll
            for (int j = 0; j < 8; j++) s += s_tmp[j * KK + tid];
            s_S0[tid] = s;
        }
        __syncthreads();
    }

    const int g    = blockIdx.x * 256 + tid;   // 0..32767
    const int task = g >> 3;                   // 0..4095 = p*256 + d
    const int sub  = g & 7;
    const int p    = task >> 8;
    const int d    = task & 255;

    const u64* src = (sub < 4 ? g_PX : g_PX2) + p * DD + d;
    float ax = 0.0f, ay = 0.0f;
    #pragma unroll 4
    for (int bb = (sub & 3); bb < GRID_MAIN; bb += 4) {
        float2 v = unpack2(src[(size_t)bb * 16 * DD]);
        ax += v.x; ay += v.y;
    }
    // combine stride-4 partials within each array
    ax += __shfl_xor_sync(0xffffffffu, ax, 1);
    ay += __shfl_xor_sync(0xffffffffu, ay, 1);
    ax += __shfl_xor_sync(0xffffffffu, ax, 2);
    ay += __shfl_xor_sync(0xffffffffu, ay, 2);
    // pull Sx2 sums (held at sub==4) over to sub==0
    float bx = __shfl_xor_sync(0xffffffffu, ax, 4);
    float by = __shfl_xor_sync(0xffffffffu, ay, 4);

    if (sub == 0) {
        const float invN   = 1.0f / (float)NROWS;
        const float invNs2 = invN * 0.70710678118654752440f;
        int k0 = 2 * p, k1 = 2 * p + 1;

        // k0: Sx=ax, Sx2=bx ; k1: Sx=ay, Sx2=by
        {
            float wv = w[k0 * DD + d], bv = b[k0 * DD + d], S0 = s_S0[k0];
            float w2 = wv * wv;
            float mu  = wv * (ax + bv * S0) * invN;
            float Ey2 = w2 * (bx + 2.0f * bv * ax + bv * bv * S0);
            out[k0 * DD + d]           = (Ey2 - S0) * invNs2;
            out[KK * DD + k0 * DD + d] = mu;
        }
        {
            float wv = w[k1 * DD + d], bv = b[k1 * DD + d], S0 = s_S0[k1];
            float w2 = wv * wv;
            float mu  = wv * (ay + bv * S0) * invN;
            float Ey2 = w2 * (by + 2.0f * bv * ay + bv * bv * S0);
            out[k1 * DD + d]           = (Ey2 - S0) * invNs2;
            out[KK * DD + k1 * DD + d] = mu;
        }
    }
}

extern "C" void kernel_launch(void* const* d_in, const int* in_sizes, int n_in,
                              void* d_out, int out_size) {
    const float* x = (const float*)d_in[0];
    const float* w = (const float*)d_in[1];
    const float* b = (const float*)d_in[2];
    float* out = (float*)d_out;
    (void)in_sizes; (void)n_in; (void)out_size;

    fisher_main<<<GRID_MAIN, 256>>>(x, w, b);
    fisher_fin<<<128, 256>>>(w, b, out);
}

// round 5
// speedup vs baseline: 1.0709x; 1.0709x over previous
#include <cuda_runtime.h>
#include <cstdint>

// FisherLayer: N=8192 rows, D=256 dims, K=32 components.
// out[0:K*D]     = mean_n gamma[n,k]*(y1^2-1)/sqrt(2)
// out[K*D:2*K*D] = mean_n gamma[n,k]*y1
// y1 = w*(x+b), gamma = softmax_k(-0.5*sum_d y1^2).
//
// Factored:
//   y4[n,k]   = -0.5*( sum_d w2*x^2 + sum_d (2*w2*b)*x + c_k ),  c_k = sum_d w2*b^2
//   S0[k], Sx[k,d] = sum_n gamma*x, Sx2[k,d] = sum_n gamma*x^2
//   out_mu    = w*(Sx + b*S0)/N
//   out_sigma = (w2*(Sx2 + 2*b*Sx + b^2*S0) - S0) / (sqrt(2)*N)
//
// main (148 persistent blocks) -> per-block partials in chunk-major scratch;
// fin (128 blocks) bulk-copies its contiguous 75.8KB region via TMA, reduces
// in shared memory, finalizes. No atomics anywhere.

#define NROWS 8192
#define DD    256
#define KK    32
#define GRID_MAIN 148
#define NBATCH (NROWS / 8)

typedef unsigned long long u64;

// scratch: g_P[chunk 0..127][row 0..147][32 float4]
//   col = p*256 + d  (p = k-pair 0..15, d = 0..255), chunk = col>>5, within = col&31
//   float4 = (Sx[2p,d], Sx[2p+1,d], Sx2[2p,d], Sx2[2p+1,d])
__device__ __align__(128) float4 g_P[128 * GRID_MAIN * 32];
__device__ float g_PS0[GRID_MAIN * KK];

__device__ __forceinline__ u64 pack2(float lo, float hi) {
    u64 r; asm("mov.b64 %0, {%1, %2};" : "=l"(r) : "f"(lo), "f"(hi)); return r;
}
__device__ __forceinline__ float2 unpack2(u64 v) {
    float2 f; asm("mov.b64 {%0, %1}, %2;" : "=f"(f.x), "=f"(f.y) : "l"(v)); return f;
}
__device__ __forceinline__ u64 fma2(u64 a, u64 b, u64 c) {
    u64 d; asm("fma.rn.f32x2 %0, %1, %2, %3;" : "=l"(d) : "l"(a), "l"(b), "l"(c)); return d;
}
__device__ __forceinline__ uint32_t smem_u32(const void* p) {
    uint32_t a;
    asm("{ .reg .u64 t; cvta.to.shared.u64 t, %1; cvt.u32.u64 %0, t; }" : "=r"(a) : "l"(p));
    return a;
}

// ---------------- main: persistent blocks, batches of 8 rows ----------------
__global__ void __launch_bounds__(256, 1) fisher_main(const float* __restrict__ x,
                                                      const float* __restrict__ w,
                                                      const float* __restrict__ b) {
    __shared__ __align__(16) u64   s_xx2[2][8 * DD];   // (x^2, x) per [r*D + d]
    __shared__ __align__(16) float s_gamma[8 * KK];    // gamma [r][k]
    __shared__ float s_part[8 * 256];                  // y4 partials [slice][r*32+k]
    __shared__ float s_cred[8 * KK];                   // c reduce / s0 reduce

    const int tid  = threadIdx.x;
    const int wrp  = tid >> 5;
    const int lane = tid & 31;

    // inline prep: per-warp slice of (a=w^2, u=2*w^2*b) in regs, c_k reduce
    u64 atu[32];
    float c_part = 0.0f;
    {
        const float* wr = w + lane * DD + wrp * 32;
        const float* br = b + lane * DD + wrp * 32;
        #pragma unroll
        for (int j = 0; j < 32; j++) {
            float wv = wr[j], bv = br[j];
            float w2 = wv * wv;
            atu[j] = pack2(w2, 2.0f * w2 * bv);
            c_part += w2 * bv * bv;
        }
    }
    s_cred[wrp * KK + lane] = c_part;

    // phase-B accumulators: thread owns d=tid; pair-packed over k
    u64 accx[16], accx2[16];
    #pragma unroll
    for (int p = 0; p < 16; p++) { accx[p] = 0ull; accx2[p] = 0ull; }
    float s0acc = 0.0f;

    int batch = blockIdx.x;
    bool have = true;

    float xr[8];
    {
        const float* xb = x + (size_t)batch * 8 * DD;
        #pragma unroll
        for (int r = 0; r < 8; r++) xr[r] = xb[r * DD + tid];
    }

    __syncthreads();
    float c_reg = 0.0f;
    #pragma unroll
    for (int j = 0; j < 8; j++) c_reg += s_cred[j * KK + lane];

    int bufsel = 0;
    while (have) {
        u64* buf = s_xx2[bufsel];
        float cx[8];
        #pragma unroll
        for (int r = 0; r < 8; r++) {
            cx[r] = xr[r];
            buf[r * DD + tid] = pack2(cx[r] * cx[r], cx[r]);
        }

        int nbatch = batch + GRID_MAIN;
        bool nhave = nbatch < NBATCH;
        if (nhave) {
            const float* xb = x + (size_t)nbatch * 8 * DD;
            #pragma unroll
            for (int r = 0; r < 8; r++) xr[r] = xb[r * DD + tid];
        }
        __syncthreads();

        // ---- phase A: y4 partial over this warp's d-slice ----
        {
            u64 accA[8];
            #pragma unroll
            for (int r = 0; r < 8; r++) accA[r] = 0ull;
            #pragma unroll
            for (int j = 0; j < 32; j += 2) {
                const int d0 = wrp * 32 + j;
                #pragma unroll
                for (int r = 0; r < 8; r++) {
                    ulonglong2 v = *reinterpret_cast<const ulonglong2*>(&buf[r * DD + d0]);
                    accA[r] = fma2(atu[j],     v.x, accA[r]);
                    accA[r] = fma2(atu[j + 1], v.y, accA[r]);
                }
            }
            #pragma unroll
            for (int r = 0; r < 8; r++) {
                float2 p = unpack2(accA[r]);
                s_part[wrp * 256 + r * 32 + lane] = p.x + p.y;
            }
        }
        __syncthreads();

        // ---- softmax: warp wrp owns row r=wrp, lane = k ----
        {
            float y = 0.0f;
            #pragma unroll
            for (int j = 0; j < 8; j++) y += s_part[j * 256 + wrp * 32 + lane];
            y = -0.5f * (y + c_reg);
            float m = y;
            #pragma unroll
            for (int o = 16; o; o >>= 1) m = fmaxf(m, __shfl_xor_sync(0xffffffffu, m, o));
            float e = __expf(y - m);
            float s = e;
            #pragma unroll
            for (int o = 16; o; o >>= 1) s += __shfl_xor_sync(0xffffffffu, s, o);
            float g = e / s;
            s0acc += g;
            s_gamma[wrp * KK + lane] = g;
        }
        __syncthreads();

        // ---- phase B: thread owns d=tid; gamma as packed float pairs ----
        #pragma unroll
        for (int r = 0; r < 8; r++) {
            float xv = cx[r];
            u64 pxx = pack2(xv, xv);
            float x2 = xv * xv;
            u64 px2 = pack2(x2, x2);
            const ulonglong2* grow = reinterpret_cast<const ulonglong2*>(&s_gamma[r * KK]);
            #pragma unroll
            for (int q = 0; q < 8; q++) {
                ulonglong2 gg = grow[q];
                accx [2 * q]     = fma2(gg.x, pxx, accx [2 * q]);
                accx [2 * q + 1] = fma2(gg.y, pxx, accx [2 * q + 1]);
                accx2[2 * q]     = fma2(gg.x, px2, accx2[2 * q]);
                accx2[2 * q + 1] = fma2(gg.y, px2, accx2[2 * q + 1]);
            }
        }

        batch = nbatch;
        have = nhave;
        bufsel ^= 1;
    }

    // ---- S0 cross-warp combine ----
    __syncthreads();
    s_cred[wrp * KK + lane] = s0acc;
    __syncthreads();
    if (wrp == 0) {
        float v = 0.0f;
        #pragma unroll
        for (int j = 0; j < 8; j++) v += s_cred[j * KK + lane];
        g_PS0[blockIdx.x * KK + lane] = v;
    }

    // ---- write partials: chunk-major, coalesced STG.128 ----
    {
        ulonglong2* pg = reinterpret_cast<ulonglong2*>(g_P);
        const int bid = blockIdx.x;
        #pragma unroll
        for (int p = 0; p < 16; p++) {
            int chunk = p * 8 + wrp;                       // col>>5
            size_t idx = ((size_t)chunk * GRID_MAIN + bid) * 32 + lane;
            ulonglong2 v; v.x = accx[p]; v.y = accx2[p];
            pg[idx] = v;
        }
    }
}

// ---------------- fin: TMA bulk reduce + finalize ----------------
// Block cb (0..127) owns chunk cb = cols [cb*32, cb*32+32): p = cb>>3 fixed,
// d in [(cb&7)*32, +32). Region g_P[cb][0..147][32] is contiguous 75776 B;
// copied in 2 waves of 74 rows (37888 B) into static smem.
__global__ void __launch_bounds__(256) fisher_fin(const float* __restrict__ w,
                                                  const float* __restrict__ bias,
                                                  float* __restrict__ out) {
    __shared__ __align__(128) float4 s_tile[74 * 32];   // 37888 B
    __shared__ float s_red[8 * KK];
    __shared__ float s_S0[KK];
    __shared__ float s_tot[2][128];
    __shared__ __align__(8) u64 s_mbar;

    const int tid = threadIdx.x;
    const int cb  = blockIdx.x;
    const uint32_t mbar = smem_u32(&s_mbar);
    const uint32_t tile = smem_u32(s_tile);
    const char* gsrc = reinterpret_cast<const char*>(g_P) + (size_t)cb * GRID_MAIN * 32 * 16;

    if (tid == 0) {
        asm volatile("mbarrier.init.shared.b64 [%0], %1;" :: "r"(mbar), "r"(1) : "memory");
        asm volatile("fence.proxy.async.shared::cta;" ::: "memory");
    }
    __syncthreads();

    // wave 0: rows 0..73
    if (tid == 0) {
        asm volatile("mbarrier.arrive.expect_tx.shared.b64 _, [%0], %1;"
                     :: "r"(mbar), "r"(74 * 512) : "memory");
        asm volatile("cp.async.bulk.shared::cluster.global.mbarrier::complete_tx::bytes "
                     "[%0], [%1], %2, [%3];"
                     :: "r"(tile), "l"(gsrc), "r"(74 * 512), "r"(mbar) : "memory");
    }

    // S0 partial reduce while TMA flies
    {
        int wrp = tid >> 5, lane = tid & 31;
        float v = 0.0f;
        for (int bb = wrp; bb < GRID_MAIN; bb += 8) v += g_PS0[bb * KK + lane];
        s_red[wrp * KK + lane] = v;
    }

    const int rc   = tid >> 7;        // 0/1: row half within tile
    const int slot = tid & 127;       // float index within 128-float row
    const float* base = reinterpret_cast<const float*>(s_tile);
    float acc = 0.0f;

    // wait wave 0 (parity 0)
    {
        uint32_t done;
        asm volatile("{ .reg .pred p; mbarrier.try_wait.parity.acquire.cta.shared::cta.b64 p, [%1], %2; selp.b32 %0, 1, 0, p; }"
                     : "=r"(done) : "r"(mbar), "r"(0) : "memory");
        if (!done) {
            asm volatile("{ .reg .pred P1; W0:\n mbarrier.try_wait.parity.acquire.cta.shared::cta.b64 P1, [%0], %1, 0x989680;\n @P1 bra.uni D0;\n bra.uni W0;\n D0: }"
                         :: "r"(mbar), "r"(0) : "memory");
        }
    }
    #pragma unroll 4
    for (int r = rc * 37; r < rc * 37 + 37; ++r) acc += base[r * 128 + slot];

    __syncthreads();   // tile reads done; s_red visible

    if (tid < KK) {
        float s = 0.0f;
        #pragma unroll
        for (int j = 0; j < 8; j++) s += s_red[j * KK + tid];
        s_S0[tid] = s;
    }

    // wave 1: rows 74..147
    if (tid == 0) {
        asm volatile("mbarrier.arrive.expect_tx.shared.b64 _, [%0], %1;"
                     :: "r"(mbar), "r"(74 * 512) : "memory");
        asm volatile("cp.async.bulk.shared::cluster.global.mbarrier::complete_tx::bytes "
                     "[%0], [%1], %2, [%3];"
                     :: "r"(tile), "l"(gsrc + 74 * 512), "r"(74 * 512), "r"(mbar) : "memory");
    }
    {
        uint32_t done;
        asm volatile("{ .reg .pred p; mbarrier.try_wait.parity.acquire.cta.shared::cta.b64 p, [%1], %2; selp.b32 %0, 1, 0, p; }"
                     : "=r"(done) : "r"(mbar), "r"(1) : "memory");
        if (!done) {
            asm volatile("{ .reg .pred P1; W1:\n mbarrier.try_wait.parity.acquire.cta.shared::cta.b64 P1, [%0], %1, 0x989680;\n @P1 bra.uni D1;\n bra.uni W1;\n D1: }"
                         :: "r"(mbar), "r"(1) : "memory");
        }
    }
    #pragma unroll 4
    for (int r = rc * 37; r < rc * 37 + 37; ++r) acc += base[r * 128 + slot];

    s_tot[rc][slot] = acc;
    __syncthreads();

    // finalize: t<64 -> (c_local = t>>1, ksel = t&1)
    if (tid < 64) {
        const int c    = tid >> 1;
        const int ksel = tid & 1;
        const int p    = cb >> 3;
        const int d    = (cb & 7) * 32 + c;
        const int k    = 2 * p + ksel;

        float Sx  = s_tot[0][c * 4 + ksel]     + s_tot[1][c * 4 + ksel];
        float Sx2 = s_tot[0][c * 4 + 2 + ksel] + s_tot[1][c * 4 + 2 + ksel];
        float S0  = s_S0[k];

        float wv = w[k * DD + d], bv = bias[k * DD + d];
        const float invN   = 1.0f / (float)NROWS;
        const float invNs2 = invN * 0.70710678118654752440f;

        float mu  = wv * (Sx + bv * S0) * invN;
        float Ey2 = wv * wv * (Sx2 + 2.0f * bv * Sx + bv * bv * S0);

        out[k * DD + d]           = (Ey2 - S0) * invNs2;
        out[KK * DD + k * DD + d] = mu;
    }
}

extern "C" void kernel_launch(void* const* d_in, const int* in_sizes, int n_in,
                              void* d_out, int out_size) {
    const float* x = (const float*)d_in[0];
    const float* w = (const float*)d_in[1];
    const float* b = (const float*)d_in[2];
    float* out = (float*)d_out;
    (void)in_sizes; (void)n_in; (void)out_size;

    fisher_main<<<GRID_MAIN, 256>>>(x, w, b);
    fisher_fin<<<128, 256>>>(w, b, out);
}